// round 6
// baseline (speedup 1.0000x reference)
#include <cuda_runtime.h>
#include <math.h>

// VectorQuantizer: inputs (16,64,64,64) fp32 (b,c,h,w), codebook (512,64) fp32.
// For each of N = 65536 spatial positions find argmin_k of the REFERENCE's
// fp32 expression  d_k = fl( fl(sumxx + cnorm_k) - 2*dot_k )  — including its
// rounding behavior (the sumxx+cnorm big-add quantization decides ~19 near-tie
// vectors, so we must reproduce it, not improve on it). dot_k is accumulated
// strictly sequentially over d=0..63 with FMA (Eigen / cuBLAS SGEMM order).
// Output: codebook[argmin] written flat (N,64).

#define CD      64
#define HW      4096
#define NCODES  512
#define THREADS 512

typedef unsigned long long u64;

// d = a*b + c  (packed fp32x2) — lanes are two CODES, accumulation per code
// stays sequential in d.
__device__ __forceinline__ u64 ffma2(u64 a, u64 b, u64 c) {
    u64 d;
    asm("fma.rn.f32x2 %0, %1, %2, %3;" : "=l"(d) : "l"(a), "l"(b), "l"(c));
    return d;
}
__device__ __forceinline__ u64 pack2(float lo, float hi) {
    u64 d;
    asm("mov.b64 %0, {%1, %2};" : "=l"(d) : "f"(lo), "f"(hi));
    return d;
}
__device__ __forceinline__ void unpack2(u64 v, float& lo, float& hi) {
    asm("mov.b64 {%0, %1}, %2;" : "=f"(lo), "=f"(hi) : "l"(v));
}

extern __shared__ float smem[];   // cbT[64][512] (transposed codebook), then cnorm[512]

__global__ void __launch_bounds__(THREADS, 1) vq_kernel(
    const float* __restrict__ in, const float* __restrict__ cb, float* __restrict__ out)
{
    const int t = threadIdx.x;
    float* cbT   = smem;                  // cbT[d*512 + k]
    float* cnorm = smem + CD * NCODES;    // cnorm[k]

    // ---- Stage codebook transposed: thread t owns code row t ----
    {
        const float4* src = (const float4*)(cb + t * CD);   // coalesced 16B reads
        #pragma unroll
        for (int j = 0; j < 16; j++) {
            float4 v = src[j];
            cbT[(4 * j + 0) * NCODES + t] = v.x;   // lanes write consecutive k -> no conflicts
            cbT[(4 * j + 1) * NCODES + t] = v.y;
            cbT[(4 * j + 2) * NCODES + t] = v.z;
            cbT[(4 * j + 3) * NCODES + t] = v.w;
        }
    }
    __syncthreads();

    // ---- cnorm_k = sum(c^2), sequential mul+add (order provably irrelevant) ----
    {
        float s = 0.f;
        #pragma unroll
        for (int d = 0; d < CD; d++) {
            float c = cbT[d * NCODES + t];
            s = __fadd_rn(s, __fmul_rn(c, c));
        }
        cnorm[t] = s;
    }
    __syncthreads();

    // ---- Load this thread's x (channel column, stride HW); sumxx sequential ----
    const int b  = blockIdx.x >> 3;
    const int s0 = (blockIdx.x & 7) * THREADS;
    const float* xin = in + (size_t)b * (CD * HW) + s0 + t;
    float x[CD];
    float sumxx = 0.f;
    #pragma unroll
    for (int d = 0; d < CD; d++) {
        x[d] = __ldg(xin + d * HW);               // coalesced across warp
        sumxx = __fadd_rn(sumxx, __fmul_rn(x[d], x[d]));
    }

    // ---- Main loop: 16 codes per tile (8 f32x2 accumulators), d sequential ----
    float best = INFINITY;
    int   bi   = 0;

    for (int k0 = 0; k0 < NCODES; k0 += 16) {
        u64 acc[8];
        #pragma unroll
        for (int q = 0; q < 8; q++) acc[q] = 0ull;

        #pragma unroll
        for (int d = 0; d < CD; d++) {
            u64 xx = pack2(x[d], x[d]);
            const ulonglong2* row = (const ulonglong2*)(cbT + d * NCODES + k0);
            #pragma unroll
            for (int r = 0; r < 4; r++) {         // LDS.128 broadcast: 4 codes
                ulonglong2 c4 = row[r];
                acc[2 * r]     = ffma2(xx, c4.x, acc[2 * r]);      // codes k0+4r, +1
                acc[2 * r + 1] = ffma2(xx, c4.y, acc[2 * r + 1]);  // codes k0+4r+2, +3
            }
        }

        // Epilogue: reference-exact  d = fl( fl(sumxx + cnorm) - 2*dot ),
        // ascending k with strict '<' => first-min tie-break (argmin semantics).
        #pragma unroll
        for (int r = 0; r < 4; r++) {
            float d0, d1, d2, d3;
            unpack2(acc[2 * r],     d0, d1);
            unpack2(acc[2 * r + 1], d2, d3);
            int k = k0 + 4 * r;
            float v;
            v = __fsub_rn(__fadd_rn(sumxx, cnorm[k + 0]), __fmul_rn(2.f, d0));
            if (v < best) { best = v; bi = k + 0; }
            v = __fsub_rn(__fadd_rn(sumxx, cnorm[k + 1]), __fmul_rn(2.f, d1));
            if (v < best) { best = v; bi = k + 1; }
            v = __fsub_rn(__fadd_rn(sumxx, cnorm[k + 2]), __fmul_rn(2.f, d2));
            if (v < best) { best = v; bi = k + 2; }
            v = __fsub_rn(__fadd_rn(sumxx, cnorm[k + 3]), __fmul_rn(2.f, d3));
            if (v < best) { best = v; bi = k + 3; }
        }
    }

    // ---- Write codebook[bi] to out[(b*HW + s0 + t)*64 ...] (global gather, L2-hot) ----
    {
        const float4* src = (const float4*)(cb + (size_t)bi * CD);
        float4* dst = (float4*)(out + ((size_t)(b * HW + s0 + t)) * CD);
        #pragma unroll
        for (int j = 0; j < 16; j++) dst[j] = __ldg(src + j);
    }
}

extern "C" void kernel_launch(void* const* d_in, const int* in_sizes, int n_in,
                              void* d_out, int out_size)
{
    const float* in = (const float*)d_in[0];   // inputs (16,64,64,64) fp32
    const float* cb = (const float*)d_in[1];   // codebook (512,64) fp32
    float* out = (float*)d_out;

    const int smem_bytes = (CD * NCODES + NCODES) * sizeof(float);  // 130 KB + 2 KB
    cudaFuncSetAttribute(vq_kernel, cudaFuncAttributeMaxDynamicSharedMemorySize, smem_bytes);
    vq_kernel<<<128, THREADS, smem_bytes>>>(in, cb, out);
}

// round 8
// speedup vs baseline: 1.4290x; 1.4290x over previous
#include <cuda_runtime.h>
#include <math.h>

// VectorQuantizer: inputs (16,64,64,64) fp32 (b,c,h,w), codebook (512,64) fp32.
// Bit-exact replication of the reference's fp32 argmin (R6: rel_err == 0.0):
//   d_k = fl( fl(sumxx + cnorm_k) - 2*dot_k ), dot_k accumulated sequentially
//   over d=0..63 with FMA; first-min tie-break.
// R7 change: V=2 register blocking — each thread owns TWO x-vectors so every
// codebook value loaded from SMEM (LDS.128) feeds FFMA2s for both vectors.
// This halves LDS traffic per MAC (R6 was L1-bound at 80.2% with fma at 37.7%).

#define CD      64
#define HW      4096
#define NCODES  512
#define THREADS 256   // 256 threads x V=2 vectors = 512 vectors/block, 128 blocks

typedef unsigned long long u64;

// d = a*b + c  (packed fp32x2); lanes are two CODES, per-code accumulation
// stays strictly sequential in d (reference rounding order).
__device__ __forceinline__ u64 ffma2(u64 a, u64 b, u64 c) {
    u64 d;
    asm("fma.rn.f32x2 %0, %1, %2, %3;" : "=l"(d) : "l"(a), "l"(b), "l"(c));
    return d;
}
__device__ __forceinline__ u64 pack2(float lo, float hi) {
    u64 d;
    asm("mov.b64 %0, {%1, %2};" : "=l"(d) : "f"(lo), "f"(hi));
    return d;
}
__device__ __forceinline__ void unpack2(u64 v, float& lo, float& hi) {
    asm("mov.b64 {%0, %1}, %2;" : "=f"(lo), "=f"(hi) : "l"(v));
}

extern __shared__ float smem[];   // cbT[64][512] transposed codebook, then cnorm[512]

__global__ void __launch_bounds__(THREADS, 1) vq_kernel(
    const float* __restrict__ in, const float* __restrict__ cb, float* __restrict__ out)
{
    const int t = threadIdx.x;
    float* cbT   = smem;                  // cbT[d*512 + k]
    float* cnorm = smem + CD * NCODES;    // cnorm[k]

    // ---- Stage codebook transposed: thread t owns code rows t and t+256 ----
    #pragma unroll
    for (int h = 0; h < 2; h++) {
        const int k = t + h * 256;
        const float4* src = (const float4*)(cb + k * CD);   // coalesced 16B reads
        #pragma unroll
        for (int j = 0; j < 16; j++) {
            float4 v = src[j];
            cbT[(4 * j + 0) * NCODES + k] = v.x;   // consecutive k per lane -> conflict-free
            cbT[(4 * j + 1) * NCODES + k] = v.y;
            cbT[(4 * j + 2) * NCODES + k] = v.z;
            cbT[(4 * j + 3) * NCODES + k] = v.w;
        }
    }
    __syncthreads();

    // ---- cnorm_k = sum(c^2), sequential mul+add (order-insensitive for argmin) ----
    #pragma unroll
    for (int h = 0; h < 2; h++) {
        const int k = t + h * 256;
        float s = 0.f;
        #pragma unroll
        for (int d = 0; d < CD; d++) {
            float c = cbT[d * NCODES + k];
            s = __fadd_rn(s, __fmul_rn(c, c));
        }
        cnorm[k] = s;
    }
    __syncthreads();

    // ---- Load TWO x vectors (channel columns, stride HW); sumxx sequential ----
    const int b  = blockIdx.x >> 3;
    const int s0 = (blockIdx.x & 7) * 512;         // 512 vectors per block
    const float* xin0 = in + (size_t)b * (CD * HW) + s0 + t;        // vector s0+t
    const float* xin1 = xin0 + 256;                                  // vector s0+t+256
    float xa[CD], xb[CD];
    float sxa = 0.f, sxb = 0.f;
    #pragma unroll
    for (int d = 0; d < CD; d++) {
        xa[d] = __ldg(xin0 + d * HW);              // coalesced across warp
        xb[d] = __ldg(xin1 + d * HW);
        sxa = __fadd_rn(sxa, __fmul_rn(xa[d], xa[d]));
        sxb = __fadd_rn(sxb, __fmul_rn(xb[d], xb[d]));
    }

    // ---- Main loop: 16 codes/tile, each LDS.128 feeds BOTH vectors ----
    float bestA = INFINITY, bestB = INFINITY;
    int   biA   = 0,        biB   = 0;

    for (int k0 = 0; k0 < NCODES; k0 += 16) {
        u64 aA[8], aB[8];
        #pragma unroll
        for (int q = 0; q < 8; q++) { aA[q] = 0ull; aB[q] = 0ull; }

        #pragma unroll
        for (int d = 0; d < CD; d++) {
            u64 x2a = pack2(xa[d], xa[d]);
            u64 x2b = pack2(xb[d], xb[d]);
            const ulonglong2* row = (const ulonglong2*)(cbT + d * NCODES + k0);
            #pragma unroll
            for (int r = 0; r < 4; r++) {          // LDS.128: 4 codes at this d
                ulonglong2 c4 = row[r];
                aA[2 * r]     = ffma2(x2a, c4.x, aA[2 * r]);
                aA[2 * r + 1] = ffma2(x2a, c4.y, aA[2 * r + 1]);
                aB[2 * r]     = ffma2(x2b, c4.x, aB[2 * r]);
                aB[2 * r + 1] = ffma2(x2b, c4.y, aB[2 * r + 1]);
            }
        }

        // Epilogue: reference-exact  v = fl( fl(sumxx + cnorm) - 2*dot ),
        // ascending k, strict '<' => first-min tie-break.
        #pragma unroll
        for (int r = 0; r < 4; r++) {
            const int k = k0 + 4 * r;
            float a0, a1, a2, a3, b0, b1, b2, b3;
            unpack2(aA[2 * r],     a0, a1);
            unpack2(aA[2 * r + 1], a2, a3);
            unpack2(aB[2 * r],     b0, b1);
            unpack2(aB[2 * r + 1], b2, b3);
            float v;
            v = __fsub_rn(__fadd_rn(sxa, cnorm[k + 0]), __fmul_rn(2.f, a0));
            if (v < bestA) { bestA = v; biA = k + 0; }
            v = __fsub_rn(__fadd_rn(sxa, cnorm[k + 1]), __fmul_rn(2.f, a1));
            if (v < bestA) { bestA = v; biA = k + 1; }
            v = __fsub_rn(__fadd_rn(sxa, cnorm[k + 2]), __fmul_rn(2.f, a2));
            if (v < bestA) { bestA = v; biA = k + 2; }
            v = __fsub_rn(__fadd_rn(sxa, cnorm[k + 3]), __fmul_rn(2.f, a3));
            if (v < bestA) { bestA = v; biA = k + 3; }

            v = __fsub_rn(__fadd_rn(sxb, cnorm[k + 0]), __fmul_rn(2.f, b0));
            if (v < bestB) { bestB = v; biB = k + 0; }
            v = __fsub_rn(__fadd_rn(sxb, cnorm[k + 1]), __fmul_rn(2.f, b1));
            if (v < bestB) { bestB = v; biB = k + 1; }
            v = __fsub_rn(__fadd_rn(sxb, cnorm[k + 2]), __fmul_rn(2.f, b2));
            if (v < bestB) { bestB = v; biB = k + 2; }
            v = __fsub_rn(__fadd_rn(sxb, cnorm[k + 3]), __fmul_rn(2.f, b3));
            if (v < bestB) { bestB = v; biB = k + 3; }
        }
    }

    // ---- Write winning codebook rows (gather from L2-hot cb) ----
    {
        const float4* srcA = (const float4*)(cb + (size_t)biA * CD);
        const float4* srcB = (const float4*)(cb + (size_t)biB * CD);
        float4* dstA = (float4*)(out + ((size_t)(b * HW + s0 + t))       * CD);
        float4* dstB = (float4*)(out + ((size_t)(b * HW + s0 + t + 256)) * CD);
        #pragma unroll
        for (int j = 0; j < 16; j++) dstA[j] = __ldg(srcA + j);
        #pragma unroll
        for (int j = 0; j < 16; j++) dstB[j] = __ldg(srcB + j);
    }
}

extern "C" void kernel_launch(void* const* d_in, const int* in_sizes, int n_in,
                              void* d_out, int out_size)
{
    const float* in = (const float*)d_in[0];   // inputs (16,64,64,64) fp32
    const float* cb = (const float*)d_in[1];   // codebook (512,64) fp32
    float* out = (float*)d_out;

    const int smem_bytes = (CD * NCODES + NCODES) * sizeof(float);  // 130 KB + 2 KB
    cudaFuncSetAttribute(vq_kernel, cudaFuncAttributeMaxDynamicSharedMemorySize, smem_bytes);
    vq_kernel<<<128, THREADS, smem_bytes>>>(in, cb, out);
}